// round 3
// baseline (speedup 1.0000x reference)
#include <cuda_runtime.h>

#define BM 128
#define BN 128
#define BK 16
#define NTHREADS 256

// ---------------------------------------------------------------------------
// KAN inner activation: inner = c0*B0(tanh(x)) + c1*B1(tanh(x))
// Cubic (order-3) Cox-de Boor on uniform knots linspace(-1,1,8), n_active=2.
// ---------------------------------------------------------------------------
__device__ __forceinline__ float kan_act(float xv, float c0, float c1) {
    // accurate-enough tanh independent of fast-math flags:
    // tanh(x) = 1 - 2/(exp(2x)+1);  abs err ~1e-6, spline is C2 so fine.
    float e = __expf(2.0f * xv);
    float t = 1.0f - __fdividef(2.0f, e + 1.0f);

    const float K0 = -1.0f;
    const float K1 = (float)(-1.0 + 1.0 * (2.0 / 7.0));
    const float K2 = (float)(-1.0 + 2.0 * (2.0 / 7.0));
    const float K3 = (float)(-1.0 + 3.0 * (2.0 / 7.0));
    const float K4 = (float)(-1.0 + 4.0 * (2.0 / 7.0));
    const float K5 = (float)(-1.0 + 5.0 * (2.0 / 7.0));
    const float I1 = 3.5f;                  // 1/h,  h = 2/7
    const float I2 = 1.75f;                 // 1/(2h)
    const float I3 = (float)(7.0 / 6.0);    // 1/(3h)

    // order 0 indicators (half-open intervals, matching reference)
    float b00 = (t >= K0 && t < K1) ? 1.0f : 0.0f;
    float b01 = (t >= K1 && t < K2) ? 1.0f : 0.0f;
    float b02 = (t >= K2 && t < K3) ? 1.0f : 0.0f;
    float b03 = (t >= K3 && t < K4) ? 1.0f : 0.0f;
    float b04 = (t >= K4 && t < K5) ? 1.0f : 0.0f;
    // order 1
    float b10 = ((t - K0) * b00 + (K2 - t) * b01) * I1;
    float b11 = ((t - K1) * b01 + (K3 - t) * b02) * I1;
    float b12 = ((t - K2) * b02 + (K4 - t) * b03) * I1;
    float b13 = ((t - K3) * b03 + (K5 - t) * b04) * I1;
    // order 2
    float b20 = ((t - K0) * b10 + (K3 - t) * b11) * I2;
    float b21 = ((t - K1) * b11 + (K4 - t) * b12) * I2;
    float b22 = ((t - K2) * b12 + (K5 - t) * b13) * I2;
    // order 3 (only k=0,1 are active)
    float b30 = ((t - K0) * b20 + (K4 - t) * b21) * I3;
    float b31 = ((t - K1) * b21 + (K5 - t) * b22) * I3;

    return c0 * b30 + c1 * b31;
}

// ---------------------------------------------------------------------------
// Fused kernel: C[m,n] = sum_k kan_act(x[m,k]; ic[k]) * W[n,k]
// Classic SGEMM tiling, activation fused into the A-tile global load.
// ---------------------------------------------------------------------------
__global__ void __launch_bounds__(NTHREADS, 2)
kan_fused_sgemm(const float* __restrict__ x,
                const float* __restrict__ ic,   // [256,5] inner coeffs
                const float* __restrict__ oc,   // [N,256] outer coeffs
                float* __restrict__ out,
                int K_dim)                      // = 256
{
    __shared__ float As[BK][BM];
    __shared__ float Bs[BK][BN];
    __shared__ float c0s[256];
    __shared__ float c1s[256];

    const int tid = threadIdx.x;
    const int m0 = blockIdx.y * BM;
    const int n0 = blockIdx.x * BN;

    // stage inner coeffs (only first 2 of 5 columns are active)
    c0s[tid] = ic[tid * 5 + 0];
    c1s[tid] = ic[tid * 5 + 1];
    __syncthreads();

    const int ty = tid >> 4;   // 0..15  -> M fragment
    const int tx = tid & 15;   // 0..15  -> N fragment

    float acc[8][8];
#pragma unroll
    for (int i = 0; i < 8; i++)
#pragma unroll
        for (int j = 0; j < 8; j++) acc[i][j] = 0.0f;

    for (int kt = 0; kt < K_dim; kt += BK) {
        // ---- load + activate A tile: As[k][m] = act(x[m0+m, kt+k]) ----
#pragma unroll
        for (int l = 0; l < 2; l++) {
            int idx = tid + l * NTHREADS;
            int row = idx >> 2;        // 0..127
            int c4  = idx & 3;         // 0..3
            const float4 xv = *reinterpret_cast<const float4*>(
                &x[(size_t)(m0 + row) * K_dim + kt + c4 * 4]);
            int kb = kt + c4 * 4;
            As[c4 * 4 + 0][row] = kan_act(xv.x, c0s[kb + 0], c1s[kb + 0]);
            As[c4 * 4 + 1][row] = kan_act(xv.y, c0s[kb + 1], c1s[kb + 1]);
            As[c4 * 4 + 2][row] = kan_act(xv.z, c0s[kb + 2], c1s[kb + 2]);
            As[c4 * 4 + 3][row] = kan_act(xv.w, c0s[kb + 3], c1s[kb + 3]);
        }
        // ---- load B tile: Bs[k][n] = W[n0+n, kt+k] ----
#pragma unroll
        for (int l = 0; l < 2; l++) {
            int idx = tid + l * NTHREADS;
            int row = idx >> 2;
            int c4  = idx & 3;
            const float4 wv = *reinterpret_cast<const float4*>(
                &oc[(size_t)(n0 + row) * K_dim + kt + c4 * 4]);
            Bs[c4 * 4 + 0][row] = wv.x;
            Bs[c4 * 4 + 1][row] = wv.y;
            Bs[c4 * 4 + 2][row] = wv.z;
            Bs[c4 * 4 + 3][row] = wv.w;
        }
        __syncthreads();

#pragma unroll
        for (int kk = 0; kk < BK; kk++) {
            float4 a0 = *reinterpret_cast<const float4*>(&As[kk][ty * 8 + 0]);
            float4 a1 = *reinterpret_cast<const float4*>(&As[kk][ty * 8 + 4]);
            float4 b0 = *reinterpret_cast<const float4*>(&Bs[kk][tx * 8 + 0]);
            float4 b1 = *reinterpret_cast<const float4*>(&Bs[kk][tx * 8 + 4]);
            float a[8] = {a0.x, a0.y, a0.z, a0.w, a1.x, a1.y, a1.z, a1.w};
            float b[8] = {b0.x, b0.y, b0.z, b0.w, b1.x, b1.y, b1.z, b1.w};
#pragma unroll
            for (int i = 0; i < 8; i++)
#pragma unroll
                for (int j = 0; j < 8; j++)
                    acc[i][j] = fmaf(a[i], b[j], acc[i][j]);
        }
        __syncthreads();
    }

    // ---- epilogue: coalesced float4 stores ----
#pragma unroll
    for (int i = 0; i < 8; i++) {
        size_t off = (size_t)(m0 + ty * 8 + i) * (size_t)(gridDim.x * BN) + n0 + tx * 8;
        float4 v0 = make_float4(acc[i][0], acc[i][1], acc[i][2], acc[i][3]);
        float4 v1 = make_float4(acc[i][4], acc[i][5], acc[i][6], acc[i][7]);
        *reinterpret_cast<float4*>(&out[off + 0]) = v0;
        *reinterpret_cast<float4*>(&out[off + 4]) = v1;
    }
}

extern "C" void kernel_launch(void* const* d_in, const int* in_sizes, int n_in,
                              void* d_out, int out_size) {
    const float* x  = (const float*)d_in[0];  // [B,S,IN] fp32
    const float* ic = (const float*)d_in[1];  // [IN,5]  fp32
    const float* oc = (const float*)d_in[2];  // [OUT,IN] fp32
    float* out = (float*)d_out;

    const int IN  = 256;
    const int M   = in_sizes[0] / IN;   // 65536
    const int OUT = in_sizes[2] / IN;   // 256

    dim3 grid(OUT / BN, M / BM);        // (2, 512)
    kan_fused_sgemm<<<grid, NTHREADS>>>(x, ic, oc, out, IN);
}

// round 5
// speedup vs baseline: 2.0346x; 2.0346x over previous
#include <cuda_runtime.h>
#include <cuda_bf16.h>
#include <cstdint>

// ---------------------------------------------------------------------------
// Problem constants
// ---------------------------------------------------------------------------
#define KDIM 256
#define NDIM 256
#define KC   64                    // K chunk: 64 bf16 = 128B row
#define NCHUNK (KDIM / KC)
#define NTHR 512                   // 16 warps

// SMEM layout (bytes)
#define OFF_TAB   0
#define TAB_BYTES (256 * 6 * 16)                 // 24576
#define OFF_A     24576
#define A_SPLIT   (128 * 128)                    // 16384 (128 rows x 128B)
#define A_STAGE   (2 * A_SPLIT)                  // hi + lo
#define OFF_B     (OFF_A + 2 * A_STAGE)          // 90112
#define B_SPLIT   (256 * 128)                    // 32768
#define B_STAGE   (2 * B_SPLIT)
#define SMEM_TOTAL (OFF_B + 2 * B_STAGE)         // 221184

// ---------------------------------------------------------------------------
// Prologue outputs: pre-split + pre-swizzled B images, activation table
// ---------------------------------------------------------------------------
__device__ __align__(16) unsigned char g_Bh[NCHUNK][B_SPLIT];
__device__ __align__(16) unsigned char g_Bl[NCHUNK][B_SPLIT];
__device__ __align__(16) float4 g_tab[256 * 6];

// ---------------------------------------------------------------------------
// helpers
// ---------------------------------------------------------------------------
__device__ __forceinline__ uint32_t smem_u32(const void* p) {
    uint32_t a;
    asm("{ .reg .u64 t; cvta.to.shared.u64 t, %1; cvt.u32.u64 %0, t; }" : "=r"(a) : "l"(p));
    return a;
}

__device__ __forceinline__ void ldsm_x4(uint32_t& r0, uint32_t& r1, uint32_t& r2,
                                        uint32_t& r3, uint32_t addr) {
    asm volatile("ldmatrix.sync.aligned.m8n8.x4.shared.b16 {%0,%1,%2,%3}, [%4];"
                 : "=r"(r0), "=r"(r1), "=r"(r2), "=r"(r3) : "r"(addr));
}

__device__ __forceinline__ void mma_bf16(float* c, const uint32_t* a,
                                         uint32_t b0, uint32_t b1) {
    asm volatile(
        "mma.sync.aligned.m16n8k16.row.col.f32.bf16.bf16.f32 "
        "{%0,%1,%2,%3}, {%4,%5,%6,%7}, {%8,%9}, {%0,%1,%2,%3};"
        : "+f"(c[0]), "+f"(c[1]), "+f"(c[2]), "+f"(c[3])
        : "r"(a[0]), "r"(a[1]), "r"(a[2]), "r"(a[3]), "r"(b0), "r"(b1));
}

#define CP_ASYNC16(saddr, gptr) \
    asm volatile("cp.async.cg.shared.global [%0], [%1], 16;" :: "r"(saddr), "l"(gptr))
#define CP_COMMIT() asm volatile("cp.async.commit_group;")
#define CP_WAIT(n)  asm volatile("cp.async.wait_group %0;" :: "n"(n))

__device__ __forceinline__ void split_pack(float a0, float a1, uint32_t& hi, uint32_t& lo) {
    __nv_bfloat16 h0 = __float2bfloat16(a0);
    __nv_bfloat16 h1 = __float2bfloat16(a1);
    __nv_bfloat16 l0 = __float2bfloat16(a0 - __bfloat162float(h0));
    __nv_bfloat16 l1 = __float2bfloat16(a1 - __bfloat162float(h1));
    hi = ((uint32_t)__bfloat16_as_ushort(h1) << 16) | (uint32_t)__bfloat16_as_ushort(h0);
    lo = ((uint32_t)__bfloat16_as_ushort(l1) << 16) | (uint32_t)__bfloat16_as_ushort(l0);
}

// ---------------------------------------------------------------------------
// Prologue: B split/swizzle images + per-channel piecewise-cubic table
// ---------------------------------------------------------------------------
__global__ void kan_prologue(const float* __restrict__ ic, const float* __restrict__ oc) {
    if (blockIdx.x < 32) {
        int gid = blockIdx.x * 256 + threadIdx.x;   // 0..8191
        int n   = gid >> 5;                          // 0..255
        int g   = gid & 31;                          // k-granule (8 fp32)
        int chunk = g >> 3;
        int colg  = g & 7;
        const float4* src = (const float4*)(oc + n * KDIM + g * 8);
        float4 v0 = src[0], v1 = src[1];
        float a[8] = {v0.x, v0.y, v0.z, v0.w, v1.x, v1.y, v1.z, v1.w};
        uint32_t h[4], l[4];
#pragma unroll
        for (int e = 0; e < 4; e++) split_pack(a[2 * e], a[2 * e + 1], h[e], l[e]);
        int off = n * 128 + ((colg ^ (n & 7)) << 4);
        *(uint4*)(g_Bh[chunk] + off) = make_uint4(h[0], h[1], h[2], h[3]);
        *(uint4*)(g_Bl[chunk] + off) = make_uint4(l[0], l[1], l[2], l[3]);
    } else {
        // tab[k][j] = c0*S_j + c1*S_{j-1} (uniform cubic B-spline segments /6)
        int k = threadIdx.x;
        float c0 = ic[k * 5 + 0];
        float c1 = ic[k * 5 + 1];
        const float P[4][4] = {
            {0.f, 0.f, 0.f,  1.f},
            {1.f, 3.f, 3.f, -3.f},
            {4.f, 0.f, -6.f, 3.f},
            {1.f, -3.f, 3.f, -1.f}
        };
        const float s6 = 1.0f / 6.0f;
#pragma unroll
        for (int j = 0; j < 6; j++) {
            float q[4] = {0.f, 0.f, 0.f, 0.f};
            if (j <= 3)
                for (int d = 0; d < 4; d++) q[d] += c0 * P[j][d];
            if (j >= 1 && j <= 4)
                for (int d = 0; d < 4; d++) q[d] += c1 * P[j - 1][d];
            g_tab[k * 6 + j] = make_float4(q[0] * s6, q[1] * s6, q[2] * s6, q[3] * s6);
        }
    }
}

// ---------------------------------------------------------------------------
__device__ __forceinline__ float kan_eval(float xv, const float4* __restrict__ tab, int k) {
    float e2 = __expf(2.0f * xv);
    float t  = 1.0f - __fdividef(2.0f, e2 + 1.0f);   // tanh
    float v  = fmaf(t, 3.5f, 3.5f);                   // (t+1)/h
    int j = (int)v;
    j = j > 5 ? 5 : j;                                // slot 5 == zeros
    float u = v - (float)j;
    float4 p = tab[k * 6 + j];
    return fmaf(fmaf(fmaf(p.w, u, p.z), u, p.y), u, p.x);
}

// ---------------------------------------------------------------------------
// Main: CTA computes C[128 x 256] = act(X[128 x 256]) @ W^T via HMMA bf16
// ---------------------------------------------------------------------------
__global__ void __launch_bounds__(NTHR, 1)
kan_main(const float* __restrict__ x, float* __restrict__ out) {
    extern __shared__ __align__(1024) char smem[];
    const int tid = threadIdx.x;
    const int wid = tid >> 5;
    const int lid = tid & 31;
    const int m0  = blockIdx.x * 128;

    const uint32_t sbase = smem_u32(smem);

    // warp tile: 32 (M) x 64 (N)
    const int wm = (wid >> 2) * 32;
    const int wn = (wid & 3) * 64;

    // ---- stage table ----
    {
        float4* stab = (float4*)(smem + OFF_TAB);
#pragma unroll
        for (int i = 0; i < 3; i++) stab[tid + i * NTHR] = g_tab[tid + i * NTHR];
    }
    // ---- issue B chunk 0 ----
    {
        uint32_t dh = sbase + OFF_B;                 // buf 0, hi
#pragma unroll
        for (int i = 0; i < 4; i++) {
            int idx = tid + i * NTHR;                // 0..2047
            CP_ASYNC16(dh + idx * 16,           (const char*)g_Bh[0] + idx * 16);
            CP_ASYNC16(dh + B_SPLIT + idx * 16, (const char*)g_Bl[0] + idx * 16);
        }
        CP_COMMIT();
    }

    // ---- x prefetch chunk 0 ----
    const int arow = tid >> 2;          // 0..127
    const int aq   = tid & 3;           // k-quarter (16 elems)
    const float4* xbase = (const float4*)(x + (size_t)(m0 + arow) * KDIM + aq * 16);
    float4 xv0 = xbase[0], xv1 = xbase[1], xv2 = xbase[2], xv3 = xbase[3];

    __syncthreads();                    // table visible
    const float4* tab = (const float4*)(smem + OFF_TAB);

    float acc[2][8][4];
#pragma unroll
    for (int mt = 0; mt < 2; mt++)
#pragma unroll
        for (int nt = 0; nt < 8; nt++)
#pragma unroll
            for (int e = 0; e < 4; e++) acc[mt][nt][e] = 0.0f;

    // per-thread ldmatrix lane addressing pieces
    const int lr   = lid & 15;          // row within 16
    const int lhal = lid >> 4;          // k-granule half

    for (int c = 0; c < NCHUNK; c++) {
        const int s = c & 1;

        // ---- activation: 16 elems/thread -> A hi/lo, swizzled ----
        {
            float av[16] = {xv0.x, xv0.y, xv0.z, xv0.w, xv1.x, xv1.y, xv1.z, xv1.w,
                            xv2.x, xv2.y, xv2.z, xv2.w, xv3.x, xv3.y, xv3.z, xv3.w};
            int kb = c * KC + aq * 16;
            float r[16];
#pragma unroll
            for (int e = 0; e < 16; e++) r[e] = kan_eval(av[e], tab, kb + e);
            uint32_t h[8], l[8];
#pragma unroll
            for (int e = 0; e < 8; e++) split_pack(r[2 * e], r[2 * e + 1], h[e], l[e]);
            char* ah = smem + OFF_A + s * A_STAGE + arow * 128;
            int g0 = (aq * 2)     ^ (arow & 7);
            int g1 = (aq * 2 + 1) ^ (arow & 7);
            *(uint4*)(ah + (g0 << 4)) = make_uint4(h[0], h[1], h[2], h[3]);
            *(uint4*)(ah + (g1 << 4)) = make_uint4(h[4], h[5], h[6], h[7]);
            *(uint4*)(ah + A_SPLIT + (g0 << 4)) = make_uint4(l[0], l[1], l[2], l[3]);
            *(uint4*)(ah + A_SPLIT + (g1 << 4)) = make_uint4(l[4], l[5], l[6], l[7]);
        }
        __syncthreads();                 // A(c) visible; all mma(c-1) complete

        // ---- prefetch chunk c+1 (B via cp.async, x via LDG) ----
        if (c < NCHUNK - 1) {
            uint32_t dh = sbase + OFF_B + (s ^ 1) * B_STAGE;
#pragma unroll
            for (int i = 0; i < 4; i++) {
                int idx = tid + i * NTHR;
                CP_ASYNC16(dh + idx * 16,           (const char*)g_Bh[c + 1] + idx * 16);
                CP_ASYNC16(dh + B_SPLIT + idx * 16, (const char*)g_Bl[c + 1] + idx * 16);
            }
            CP_COMMIT();
            const float4* xp = xbase + (c + 1) * (KC / 4);
            xv0 = xp[0]; xv1 = xp[1]; xv2 = xp[2]; xv3 = xp[3];
            CP_WAIT(1);                  // B(c) done (B(c+1) may fly)
        } else {
            CP_WAIT(0);
        }
        __syncthreads();                 // everyone's B(c) landed

        // ---- MMA over this chunk: 4 ksteps x 3 splits ----
        const uint32_t aBase = sbase + OFF_A + s * A_STAGE;
        const uint32_t bBase = sbase + OFF_B + s * B_STAGE;
#pragma unroll
        for (int ks = 0; ks < 4; ks++) {
            uint32_t ah[2][4], al[2][4];
#pragma unroll
            for (int mt = 0; mt < 2; mt++) {
                int r = wm + mt * 16 + lr;
                int g = ks * 2 + lhal;
                uint32_t off = (uint32_t)(r * 128 + (((g ^ (r & 7))) << 4));
                ldsm_x4(ah[mt][0], ah[mt][1], ah[mt][2], ah[mt][3], aBase + off);
                ldsm_x4(al[mt][0], al[mt][1], al[mt][2], al[mt][3], aBase + A_SPLIT + off);
            }
#pragma unroll
            for (int np = 0; np < 4; np++) {
                int r = wn + np * 16 + lr;
                int g = ks * 2 + lhal;
                uint32_t off = (uint32_t)(r * 128 + (((g ^ (r & 7))) << 4));
                uint32_t bh[4], bl[4];
                ldsm_x4(bh[0], bh[1], bh[2], bh[3], bBase + off);
                ldsm_x4(bl[0], bl[1], bl[2], bl[3], bBase + B_SPLIT + off);
#pragma unroll
                for (int mt = 0; mt < 2; mt++) {
#pragma unroll
                    for (int e = 0; e < 2; e++) {
                        float* cc = acc[mt][2 * np + e];
                        uint32_t b0h = e ? bh[1] : bh[0], b1h = e ? bh[3] : bh[2];
                        uint32_t b0l = e ? bl[1] : bl[0], b1l = e ? bl[3] : bl[2];
                        mma_bf16(cc, ah[mt], b0h, b1h);   // Ah*Bh
                        mma_bf16(cc, al[mt], b0h, b1h);   // Al*Bh
                        mma_bf16(cc, ah[mt], b0l, b1l);   // Ah*Bl
                    }
                }
            }
        }
        // next iteration's act writes the other A buffer; sync at its top
        // (the __syncthreads after activation) orders everything.
    }

    // ---- epilogue: direct fp32 stores from accumulators ----
    {
        const int rq = lid >> 2;            // 0..7
        const int cq = (lid & 3) * 2;       // 0,2,4,6
#pragma unroll
        for (int mt = 0; mt < 2; mt++) {
            int row = m0 + wm + mt * 16 + rq;
#pragma unroll
            for (int nt = 0; nt < 8; nt++) {
                int col = wn + nt * 8 + cq;
                float2 v0 = make_float2(acc[mt][nt][0], acc[mt][nt][1]);
                float2 v1 = make_float2(acc[mt][nt][2], acc[mt][nt][3]);
                *(float2*)(out + (size_t)row * NDIM + col)       = v0;
                *(float2*)(out + (size_t)(row + 8) * NDIM + col) = v1;
            }
        }
    }
}

// ---------------------------------------------------------------------------
extern "C" void kernel_launch(void* const* d_in, const int* in_sizes, int n_in,
                              void* d_out, int out_size) {
    const float* x  = (const float*)d_in[0];   // [B,S,256] fp32
    const float* ic = (const float*)d_in[1];   // [256,5]   fp32
    const float* oc = (const float*)d_in[2];   // [256,256] fp32
    float* out = (float*)d_out;

    const int M = in_sizes[0] / KDIM;          // 65536

    cudaFuncSetAttribute(kan_main, cudaFuncAttributeMaxDynamicSharedMemorySize, SMEM_TOTAL);

    kan_prologue<<<33, 256>>>(ic, oc);
    kan_main<<<M / 128, NTHR, SMEM_TOTAL>>>(x, out);
}

// round 6
// speedup vs baseline: 3.4713x; 1.7062x over previous
#include <cuda_runtime.h>
#include <cuda_fp16.h>
#include <cstdint>

// ---------------------------------------------------------------------------
// Problem constants
// ---------------------------------------------------------------------------
#define KDIM 256
#define NDIM 256
#define KC   64                    // K chunk: 64 fp16 = 128B row
#define NCHUNK (KDIM / KC)
#define NTHR 512                   // 16 warps

// SMEM layout (bytes)
#define OFF_TAB   0
#define TAB_BYTES (256 * 6 * 16)                 // 24576
#define OFF_A     24576
#define A_BUF     (128 * 128)                    // 16384 (128 rows x 128B)
#define OFF_B     (OFF_A + 2 * A_BUF)            // 57344
#define B_BUF     (256 * 128)                    // 32768
#define SMEM_TOTAL (OFF_B + 2 * B_BUF)           // 122880

// ---------------------------------------------------------------------------
// Prologue outputs: pre-converted + pre-swizzled fp16 B images, cubic table
// ---------------------------------------------------------------------------
__device__ __align__(16) unsigned char g_Bf[NCHUNK][B_BUF];
__device__ __align__(16) float4 g_tab[256 * 6];

// ---------------------------------------------------------------------------
// helpers
// ---------------------------------------------------------------------------
__device__ __forceinline__ uint32_t smem_u32(const void* p) {
    uint32_t a;
    asm("{ .reg .u64 t; cvta.to.shared.u64 t, %1; cvt.u32.u64 %0, t; }" : "=r"(a) : "l"(p));
    return a;
}

__device__ __forceinline__ void ldsm_x4(uint32_t& r0, uint32_t& r1, uint32_t& r2,
                                        uint32_t& r3, uint32_t addr) {
    asm volatile("ldmatrix.sync.aligned.m8n8.x4.shared.b16 {%0,%1,%2,%3}, [%4];"
                 : "=r"(r0), "=r"(r1), "=r"(r2), "=r"(r3) : "r"(addr));
}

__device__ __forceinline__ void mma_fp16(float* c, const uint32_t* a,
                                         uint32_t b0, uint32_t b1) {
    asm volatile(
        "mma.sync.aligned.m16n8k16.row.col.f32.f16.f16.f32 "
        "{%0,%1,%2,%3}, {%4,%5,%6,%7}, {%8,%9}, {%0,%1,%2,%3};"
        : "+f"(c[0]), "+f"(c[1]), "+f"(c[2]), "+f"(c[3])
        : "r"(a[0]), "r"(a[1]), "r"(a[2]), "r"(a[3]), "r"(b0), "r"(b1));
}

#define CP_ASYNC16(saddr, gptr) \
    asm volatile("cp.async.cg.shared.global [%0], [%1], 16;" :: "r"(saddr), "l"(gptr))
#define CP_COMMIT() asm volatile("cp.async.commit_group;")
#define CP_WAIT0()  asm volatile("cp.async.wait_group 0;")

__device__ __forceinline__ uint32_t pack_h2(float a0, float a1) {
    __half2 h = __floats2half2_rn(a0, a1);   // x (a0) in low 16 bits
    return *reinterpret_cast<uint32_t*>(&h);
}

// ---------------------------------------------------------------------------
// Prologue: fp16 pre-swizzled B images + per-channel piecewise-cubic table
// ---------------------------------------------------------------------------
__global__ void kan_prologue(const float* __restrict__ ic, const float* __restrict__ oc) {
    if (blockIdx.x < 32) {
        int gid = blockIdx.x * 256 + threadIdx.x;   // 0..8191
        int n   = gid >> 5;                          // B row 0..255
        int g   = gid & 31;                          // k-granule (8 fp32)
        int chunk = g >> 3;
        int colg  = g & 7;
        const float4* src = (const float4*)(oc + n * KDIM + g * 8);
        float4 v0 = src[0], v1 = src[1];
        float a[8] = {v0.x, v0.y, v0.z, v0.w, v1.x, v1.y, v1.z, v1.w};
        uint32_t h[4];
#pragma unroll
        for (int e = 0; e < 4; e++) h[e] = pack_h2(a[2 * e], a[2 * e + 1]);
        int off = n * 128 + ((colg ^ (n & 7)) << 4);
        *(uint4*)(g_Bf[chunk] + off) = make_uint4(h[0], h[1], h[2], h[3]);
    } else {
        // tab[k][j] = c0*S_j + c1*S_{j-1} (uniform cubic B-spline segments /6)
        int k = threadIdx.x;
        float c0 = ic[k * 5 + 0];
        float c1 = ic[k * 5 + 1];
        const float P[4][4] = {
            {0.f, 0.f, 0.f,  1.f},
            {1.f, 3.f, 3.f, -3.f},
            {4.f, 0.f, -6.f, 3.f},
            {1.f, -3.f, 3.f, -1.f}
        };
        const float s6 = 1.0f / 6.0f;
#pragma unroll
        for (int j = 0; j < 6; j++) {
            float q[4] = {0.f, 0.f, 0.f, 0.f};
            if (j <= 3)
                for (int d = 0; d < 4; d++) q[d] += c0 * P[j][d];
            if (j >= 1 && j <= 4)
                for (int d = 0; d < 4; d++) q[d] += c1 * P[j - 1][d];
            g_tab[k * 6 + j] = make_float4(q[0] * s6, q[1] * s6, q[2] * s6, q[3] * s6);
        }
    }
}

// ---------------------------------------------------------------------------
__device__ __forceinline__ float kan_eval(float xv, const float4* __restrict__ tab, int k) {
    float e2 = __expf(2.0f * xv);
    float t  = 1.0f - __fdividef(2.0f, e2 + 1.0f);   // tanh
    float v  = fmaf(t, 3.5f, 3.5f);                   // (t+1)/h
    int j = (int)v;
    j = j > 5 ? 5 : j;                                // slot 5 == zeros
    float u = v - (float)j;
    float4 p = tab[k * 6 + j];
    return fmaf(fmaf(fmaf(p.w, u, p.z), u, p.y), u, p.x);
}

// ---------------------------------------------------------------------------
// Main: CTA computes C[128 x 256] = act(X[128 x 256]) @ W^T, fp16 HMMA,
// activation for chunk c+1 fused into the MMA phase of chunk c.
// ---------------------------------------------------------------------------
__global__ void __launch_bounds__(NTHR, 1)
kan_main(const float* __restrict__ x, float* __restrict__ out) {
    extern __shared__ __align__(1024) char smem[];
    const int tid = threadIdx.x;
    const int wid = tid >> 5;
    const int lid = tid & 31;
    const int m0  = blockIdx.x * 128;

    const uint32_t sbase = smem_u32(smem);

    // warp tile: 32 (M) x 64 (N)
    const int wm = (wid >> 2) * 32;
    const int wn = (wid & 3) * 64;

    // ---- stage table ----
    {
        float4* stab = (float4*)(smem + OFF_TAB);
#pragma unroll
        for (int i = 0; i < 3; i++) stab[tid + i * NTHR] = g_tab[tid + i * NTHR];
    }
    // ---- issue B chunk 0 ----
    {
        uint32_t dh = sbase + OFF_B;
#pragma unroll
        for (int i = 0; i < 4; i++) {
            int idx = tid + i * NTHR;                // 0..2047
            CP_ASYNC16(dh + idx * 16, (const char*)g_Bf[0] + idx * 16);
        }
        CP_COMMIT();
    }

    // ---- x chunk 0 ----
    const int arow = tid >> 2;          // 0..127
    const int aq   = tid & 3;           // k-quarter (16 elems)
    const float4* xbase = (const float4*)(x + (size_t)(m0 + arow) * KDIM + aq * 16);
    float4 xv0 = xbase[0], xv1 = xbase[1], xv2 = xbase[2], xv3 = xbase[3];

    __syncthreads();                    // table visible
    const float4* tab = (const float4*)(smem + OFF_TAB);

    // activation writer constants
    const int g0 = aq * 2;
    const int g1 = aq * 2 + 1;
    const int swg0 = (g0 ^ (arow & 7)) << 4;
    const int swg1 = (g1 ^ (arow & 7)) << 4;

    // ---- act(0) -> A buf 0 ----
    {
        float av[16] = {xv0.x, xv0.y, xv0.z, xv0.w, xv1.x, xv1.y, xv1.z, xv1.w,
                        xv2.x, xv2.y, xv2.z, xv2.w, xv3.x, xv3.y, xv3.z, xv3.w};
        int kb = aq * 16;
        float r[16];
#pragma unroll
        for (int e = 0; e < 16; e++) r[e] = kan_eval(av[e], tab, kb + e);
        char* ad = smem + OFF_A + arow * 128;
        *(uint4*)(ad + swg0) = make_uint4(pack_h2(r[0], r[1]),  pack_h2(r[2], r[3]),
                                          pack_h2(r[4], r[5]),  pack_h2(r[6], r[7]));
        *(uint4*)(ad + swg1) = make_uint4(pack_h2(r[8], r[9]),  pack_h2(r[10], r[11]),
                                          pack_h2(r[12], r[13]), pack_h2(r[14], r[15]));
    }

    float acc[2][8][4];
#pragma unroll
    for (int mt = 0; mt < 2; mt++)
#pragma unroll
        for (int nt = 0; nt < 8; nt++)
#pragma unroll
            for (int e = 0; e < 4; e++) acc[mt][nt][e] = 0.0f;

    const int lr   = lid & 15;          // ldmatrix row within 16
    const int lhal = lid >> 4;          // k-granule half

#pragma unroll
    for (int c = 0; c < NCHUNK; c++) {
        const int s = c & 1;

        CP_WAIT0();                     // B(c) landed (only group in flight)
        __syncthreads();                // A(c)+B(c) visible; MMA(c-1) reads done

        // ---- prefetch chunk c+1: B via cp.async, x via LDG ----
        if (c < NCHUNK - 1) {
            uint32_t dh = sbase + OFF_B + (s ^ 1) * B_BUF;
#pragma unroll
            for (int i = 0; i < 4; i++) {
                int idx = tid + i * NTHR;
                CP_ASYNC16(dh + idx * 16, (const char*)g_Bf[c + 1] + idx * 16);
            }
            CP_COMMIT();
            const float4* xp = xbase + (c + 1) * (KC / 4);
            xv0 = xp[0]; xv1 = xp[1]; xv2 = xp[2]; xv3 = xp[3];
        }

        // ---- MMA(c): 4 ksteps, single fp16 pass ----
        const uint32_t aBase = sbase + OFF_A + s * A_BUF;
        const uint32_t bBase = sbase + OFF_B + s * B_BUF;
#pragma unroll
        for (int ks = 0; ks < 4; ks++) {
            const int g = ks * 2 + lhal;
            uint32_t a[2][4];
#pragma unroll
            for (int mt = 0; mt < 2; mt++) {
                int r = wm + mt * 16 + lr;
                uint32_t off = (uint32_t)(r * 128 + ((g ^ (r & 7)) << 4));
                ldsm_x4(a[mt][0], a[mt][1], a[mt][2], a[mt][3], aBase + off);
            }
#pragma unroll
            for (int np = 0; np < 4; np++) {
                int r = wn + np * 16 + lr;
                uint32_t off = (uint32_t)(r * 128 + ((g ^ (r & 7)) << 4));
                uint32_t b[4];
                ldsm_x4(b[0], b[1], b[2], b[3], bBase + off);
#pragma unroll
                for (int mt = 0; mt < 2; mt++) {
                    mma_fp16(acc[mt][2 * np + 0], a[mt], b[0], b[2]);
                    mma_fp16(acc[mt][2 * np + 1], a[mt], b[1], b[3]);
                }
            }
        }

        // ---- act(c+1) -> other A buffer (overlaps tensor-pipe drain) ----
        if (c < NCHUNK - 1) {
            float av[16] = {xv0.x, xv0.y, xv0.z, xv0.w, xv1.x, xv1.y, xv1.z, xv1.w,
                            xv2.x, xv2.y, xv2.z, xv2.w, xv3.x, xv3.y, xv3.z, xv3.w};
            int kb = (c + 1) * KC + aq * 16;
            float r[16];
#pragma unroll
            for (int e = 0; e < 16; e++) r[e] = kan_eval(av[e], tab, kb + e);
            char* ad = smem + OFF_A + (s ^ 1) * A_BUF + arow * 128;
            *(uint4*)(ad + swg0) = make_uint4(pack_h2(r[0], r[1]),  pack_h2(r[2], r[3]),
                                              pack_h2(r[4], r[5]),  pack_h2(r[6], r[7]));
            *(uint4*)(ad + swg1) = make_uint4(pack_h2(r[8], r[9]),  pack_h2(r[10], r[11]),
                                              pack_h2(r[12], r[13]), pack_h2(r[14], r[15]));
        }
    }

    // ---- epilogue: direct fp32 stores from accumulators ----
    {
        const int rq = lid >> 2;            // 0..7
        const int cq = (lid & 3) * 2;       // 0,2,4,6
#pragma unroll
        for (int mt = 0; mt < 2; mt++) {
            int row = m0 + wm + mt * 16 + rq;
#pragma unroll
            for (int nt = 0; nt < 8; nt++) {
                int col = wn + nt * 8 + cq;
                float2 v0 = make_float2(acc[mt][nt][0], acc[mt][nt][1]);
                float2 v1 = make_float2(acc[mt][nt][2], acc[mt][nt][3]);
                *(float2*)(out + (size_t)row * NDIM + col)       = v0;
                *(float2*)(out + (size_t)(row + 8) * NDIM + col) = v1;
            }
        }
    }
}

// ---------------------------------------------------------------------------
extern "C" void kernel_launch(void* const* d_in, const int* in_sizes, int n_in,
                              void* d_out, int out_size) {
    const float* x  = (const float*)d_in[0];   // [B,S,256] fp32
    const float* ic = (const float*)d_in[1];   // [256,5]   fp32
    const float* oc = (const float*)d_in[2];   // [256,256] fp32
    float* out = (float*)d_out;

    const int M = in_sizes[0] / KDIM;          // 65536

    cudaFuncSetAttribute(kan_main, cudaFuncAttributeMaxDynamicSharedMemorySize, SMEM_TOTAL);

    kan_prologue<<<33, 256>>>(ic, oc);
    kan_main<<<M / 128, NTHR, SMEM_TOTAL>>>(x, out);
}